// round 1
// baseline (speedup 1.0000x reference)
#include <cuda_runtime.h>
#include <math.h>

// Problem dims
#define T_ 8
#define B_ 32
#define D_ 768
#define M_ 8
#define S_ 2
#define L_ 2
#define H_ 8
#define HD_ 96
#define d_ 384
#define P_ 16          // M_*S_
#define KVROWS 256     // M_*B_
#define KVN 1536       // 2*D_

// ---------------- device state / scratch ----------------
__device__ float g_mem[M_*B_*D_];
__device__ float g_q[M_*B_*D_];
__device__ float g_kv[(long)M_*KVROWS*KVN];
__device__ float g_o[M_*B_*D_];
__device__ float g_attn[M_*B_*D_];
__device__ float g_h[P_*B_*d_];
__device__ float g_cat[M_*B_*D_];
__device__ float g_pa[P_*L_*B_*d_];
__device__ float g_pr[P_*L_*B_*d_];
__device__ float g_dp[P_*L_*B_*d_];
__device__ float g_sr[P_*L_*B_*d_];
__device__ float g_gb[P_*L_*B_*d_];
__device__ float g_W [(long)P_*L_*d_*d_];
__device__ float g_Wr[(long)P_*L_*d_*d_];
__device__ float g_t1[P_*B_*d_];
__device__ float g_nt[P_*B_*3*d_];
__device__ float g_mod[P_*B_*d_];
__device__ float g_asm[2*P_*B_*d_];
__device__ float g_C[(long)2*P_*d_*d_];
__device__ float g_sd[P_*d_];
__device__ float g_tmp[P_*B_*d_];
__device__ float g_outpre[M_*B_*D_];

// ---------------- generic batched tiled GEMM ----------------
// C[z] = act( scale*(A[z] @ op(W[z]) + bias[z]) + add[z] )
// TRANSB: C[i][j] = sum_k A[i][k]*W[j][k]   (W row-major [N,K])
// else  : C[i][j] = sum_k A[i][k]*W[k][j]   (W row-major [K,N])
// Tiles: BM=32, BN=64, BK=32. All M,N,K must be multiples of 32/64/32.
template<bool TRANSB>
__global__ void gemm_k(const float* __restrict__ A, long aB,
                       const float* __restrict__ W, long wB,
                       const float* __restrict__ bias, long bB,
                       const float* __restrict__ add, long adB,
                       float* __restrict__ C, long cB,
                       int N, int K, float scale, int relu)
{
    __shared__ float As[32][33];
    __shared__ float Bs[32][65];
    const int tx = threadIdx.x, ty = threadIdx.y;
    const int tid = ty*16 + tx;
    const int z = blockIdx.z;
    const float* Ab = A + (long)z*aB;
    const float* Wb = W + (long)z*wB;
    const int row0 = blockIdx.y*32, col0 = blockIdx.x*64;
    float acc0[4] = {0.f,0.f,0.f,0.f}, acc1[4] = {0.f,0.f,0.f,0.f};

    for (int k0 = 0; k0 < K; k0 += 32) {
        #pragma unroll
        for (int i = 0; i < 4; i++) {
            int e = tid + i*256; int r = e >> 5, k = e & 31;
            As[r][k] = Ab[(long)(row0 + r)*K + k0 + k];
        }
        #pragma unroll
        for (int i = 0; i < 8; i++) {
            int e = tid + i*256;
            if (TRANSB) { int j = e >> 5, k = e & 31; Bs[k][j] = Wb[(long)(col0 + j)*K + k0 + k]; }
            else        { int k = e >> 6, j = e & 63; Bs[k][j] = Wb[(long)(k0 + k)*N + col0 + j]; }
        }
        __syncthreads();
        #pragma unroll
        for (int kk = 0; kk < 32; kk++) {
            float a0 = As[ty*2][kk], a1 = As[ty*2 + 1][kk];
            #pragma unroll
            for (int c = 0; c < 4; c++) {
                float b = Bs[kk][tx*4 + c];
                acc0[c] = fmaf(a0, b, acc0[c]);
                acc1[c] = fmaf(a1, b, acc1[c]);
            }
        }
        __syncthreads();
    }
    float* Cb = C + (long)z*cB;
    #pragma unroll
    for (int r = 0; r < 2; r++) {
        int row = row0 + ty*2 + r;
        #pragma unroll
        for (int c = 0; c < 4; c++) {
            int col = col0 + tx*4 + c;
            float v = r ? acc1[c] : acc0[c];
            if (bias) v += bias[(long)z*bB + col];
            v *= scale;
            if (add)  v += add[(long)z*adB + (long)row*N + col];
            if (relu) v = fmaxf(v, 0.f);
            Cb[(long)row*N + col] = v;
        }
    }
}

// ---------------- attention core ----------------
// per (h, b, m): scores[s] = qh . kh over HD_; softmax over s (M_ slots); o = sum a*vh
__global__ void attn_core_k()
{
    int h = blockIdx.x, b = blockIdx.y, m = blockIdx.z;
    int u = threadIdx.x;   // 128 threads, 96 active
    __shared__ float red[128];
    __shared__ float sc[M_];
    float qv = (u < HD_) ? g_q[((long)(m*B_ + b))*D_ + h*HD_ + u] : 0.f;
    for (int s = 0; s < M_; s++) {
        float p = 0.f;
        if (u < HD_) p = qv * g_kv[((long)m*KVROWS + s*B_ + b)*KVN + h*HD_ + u];
        red[u] = p; __syncthreads();
        #pragma unroll
        for (int o = 64; o > 0; o >>= 1) { if (u < o) red[u] += red[u + o]; __syncthreads(); }
        if (u == 0) sc[s] = red[0];
        __syncthreads();
    }
    float mx = -1e30f;
    #pragma unroll
    for (int s = 0; s < M_; s++) mx = fmaxf(mx, sc[s]);
    float a[M_]; float sum = 0.f;
    #pragma unroll
    for (int s = 0; s < M_; s++) { a[s] = __expf(sc[s] - mx); sum += a[s]; }
    float inv = 1.f / sum;
    if (u < HD_) {
        float o = 0.f;
        #pragma unroll
        for (int s = 0; s < M_; s++)
            o += a[s] * inv * g_kv[((long)m*KVROWS + s*B_ + b)*KVN + D_ + h*HD_ + u];
        g_o[((long)(m*B_ + b))*D_ + h*HD_ + u] = o;
    }
}

// ---------------- reshapes ----------------
__global__ void a2h_k()
{
    int idx = blockIdx.x*256 + threadIdx.x;
    if (idx >= P_*B_*d_) return;
    int j = idx % d_; int b = (idx/d_) % B_; int p = idx/(B_*d_);
    int m = p / S_, s = p % S_;
    g_h[idx] = g_attn[((long)(m*B_ + b))*D_ + s*d_ + j];
}
__global__ void h2cat_k()
{
    int idx = blockIdx.x*256 + threadIdx.x;
    if (idx >= M_*B_*D_) return;
    int j = idx % d_; int s = (idx/d_) % S_; int b = (idx/D_) % B_; int m = idx/(B_*D_);
    g_cat[idx] = g_h[((long)((m*S_ + s)*B_ + b))*d_ + j];
}

// ---------------- plastic layer kernels ----------------
__global__ void gates_k(int l, const float* __restrict__ alpha)
{
    int idx = blockIdx.x*256 + threadIdx.x;
    if (idx >= P_*B_*d_) return;
    int j = idx % d_; int b = (idx/d_) % B_; int p = idx/(B_*d_);
    int pl = p*L_ + l;
    long sidx = ((long)pl*B_ + b)*d_ + j;
    const float* nt = g_nt + ((long)(p*B_ + b))*3*d_ + j*3;
    float pd = nt[0], ps = nt[1], pg = nt[2];
    float inv = 1.f / fmaxf(ps, 1e-6f);
    float dpv = tanhf(g_dp[sidx] + pd*inv);
    float srv = 1.f/(1.f + __expf(-(g_sr[sidx] + ps)));
    float gbv = 1.f/(1.f + __expf(-(g_gb[sidx] + pg*inv)));
    g_dp[sidx] = dpv; g_sr[sidx] = srv; g_gb[sidx] = gbv;
    g_mod[(long)(p*B_ + b)*d_ + j] = alpha[(long)pl*d_ + j] * dpv * srv;
}

__global__ void sd_k(int l, const float* __restrict__ decay)
{
    int p = blockIdx.x; int j = threadIdx.x; // 384 threads
    int pl = p*L_ + l;
    float s = 0.f;
    for (int b = 0; b < B_; b++) s += g_gb[((long)pl*B_ + b)*d_ + j];
    s *= (1.f/B_);
    g_sd[p*d_ + j] = decay[(long)pl*d_ + j] * (1.f/(1.f + __expf(-s)));
}

__global__ void rsm_k(int l)   // row softmax of pa (which=0) / pr (which=1) over d_
{
    int row = blockIdx.x;      // 0..P_*B_-1
    int which = blockIdx.y;
    int p = row / B_, b = row % B_;
    const float* src = (which ? g_pr : g_pa) + ((long)(p*L_ + l)*B_ + b)*d_;
    float* dst = g_asm + (long)which*P_*B_*d_ + (long)row*d_;
    int u = threadIdx.x;       // 128
    __shared__ float red[128];
    float v0 = src[u], v1 = src[u + 128], v2 = src[u + 256];
    float mx = fmaxf(v0, fmaxf(v1, v2));
    red[u] = mx; __syncthreads();
    #pragma unroll
    for (int o = 64; o > 0; o >>= 1) { if (u < o) red[u] = fmaxf(red[u], red[u + o]); __syncthreads(); }
    mx = red[0]; __syncthreads();
    float e0 = __expf(v0 - mx), e1 = __expf(v1 - mx), e2 = __expf(v2 - mx);
    red[u] = e0 + e1 + e2; __syncthreads();
    #pragma unroll
    for (int o = 64; o > 0; o >>= 1) { if (u < o) red[u] += red[u + o]; __syncthreads(); }
    float inv = 1.f / red[0];
    dst[u] = e0*inv; dst[u + 128] = e1*inv; dst[u + 256] = e2*inv;
}

// C[z][i][j] = (1/B) * sum_b asm[z][b][i] * mod[p][b][j]   (z = which*P + p)
__global__ void outer_k()
{
    int z = blockIdx.z;
    int p = z % P_;
    int i0 = blockIdx.y*32, j0 = blockIdx.x*64;
    __shared__ float a_s[32][33];
    __shared__ float m_s[32][65];
    int tid = threadIdx.x;  // 256
    const float* asrc = g_asm + (long)z*B_*d_;   // contiguous: which*P_*B_*d_ + p*B_*d_
    const float* msrc = g_mod + (long)p*B_*d_;
    #pragma unroll
    for (int t = 0; t < 4; t++) { int e = tid + t*256; int b = e >> 5, i = e & 31; a_s[b][i] = asrc[(long)b*d_ + i0 + i]; }
    #pragma unroll
    for (int t = 0; t < 8; t++) { int e = tid + t*256; int b = e >> 6, j = e & 63; m_s[b][j] = msrc[(long)b*d_ + j0 + j]; }
    __syncthreads();
    int tx = tid % 16, ty = tid / 16;
    float acc0[4] = {0.f,0.f,0.f,0.f}, acc1[4] = {0.f,0.f,0.f,0.f};
    #pragma unroll
    for (int b = 0; b < 32; b++) {
        float a0 = a_s[b][ty*2], a1 = a_s[b][ty*2 + 1];
        #pragma unroll
        for (int c = 0; c < 4; c++) {
            float mv = m_s[b][tx*4 + c];
            acc0[c] = fmaf(a0, mv, acc0[c]);
            acc1[c] = fmaf(a1, mv, acc1[c]);
        }
    }
    float* dst = g_C + (long)z*d_*d_;
    #pragma unroll
    for (int c = 0; c < 4; c++) {
        dst[(long)(i0 + ty*2    )*d_ + j0 + tx*4 + c] = acc0[c]*(1.f/B_);
        dst[(long)(i0 + ty*2 + 1)*d_ + j0 + tx*4 + c] = acc1[c]*(1.f/B_);
    }
}

// W_new[i][j] = W*(1-sd[i]) + rowsoftmax(W)[i][j]*C[i][j]
__global__ void wupd_k(int l)
{
    int i = blockIdx.x, p = blockIdx.y, which = blockIdx.z;
    float* Wp = (which ? g_Wr : g_W) + ((long)(p*L_ + l)*d_ + i)*d_;
    const float* Cp = g_C + ((long)(which*P_ + p)*d_ + i)*d_;
    int u = threadIdx.x;  // 128
    __shared__ float red[128];
    float w0 = Wp[u], w1 = Wp[u + 128], w2 = Wp[u + 256];
    float mx = fmaxf(w0, fmaxf(w1, w2));
    red[u] = mx; __syncthreads();
    #pragma unroll
    for (int o = 64; o > 0; o >>= 1) { if (u < o) red[u] = fmaxf(red[u], red[u + o]); __syncthreads(); }
    mx = red[0]; __syncthreads();
    float e0 = __expf(w0 - mx), e1 = __expf(w1 - mx), e2 = __expf(w2 - mx);
    red[u] = e0 + e1 + e2; __syncthreads();
    #pragma unroll
    for (int o = 64; o > 0; o >>= 1) { if (u < o) red[u] += red[u + o]; __syncthreads(); }
    float invs = 1.f / red[0];
    float om = 1.f - g_sd[p*d_ + i];
    Wp[u]       = w0*om + e0*invs*Cp[u];
    Wp[u + 128] = w1*om + e1*invs*Cp[u + 128];
    Wp[u + 256] = w2*om + e2*invs*Cp[u + 256];
}

// ---------------- LayerNorm ----------------
// in: contiguous rows [rows][N]. out1 addr = out1 + (row/B_)*o1Group + (row%B_)*N.
// out2 (optional): contiguous row*N. gamma/beta addr = g + (row/B_)*gGroup + j.
__global__ void ln_k(const float* __restrict__ in,
                     float* __restrict__ out1, long o1Group,
                     float* __restrict__ out2,
                     const float* __restrict__ gam, const float* __restrict__ bet,
                     long gGroup, int N)
{
    int row = blockIdx.x;
    int u = threadIdx.x;   // 128
    int grp = row / B_, rb = row % B_;
    const float* x = in + (long)row*N;
    int nper = N / 128;    // 3 or 6
    float vals[6];
    float s = 0.f;
    for (int t = 0; t < nper; t++) { vals[t] = x[u + t*128]; s += vals[t]; }
    __shared__ float red[128];
    red[u] = s; __syncthreads();
    #pragma unroll
    for (int o = 64; o > 0; o >>= 1) { if (u < o) red[u] += red[u + o]; __syncthreads(); }
    float mu = red[0] / N; __syncthreads();
    float sq = 0.f;
    for (int t = 0; t < nper; t++) { float dv = vals[t] - mu; sq += dv*dv; }
    red[u] = sq; __syncthreads();
    #pragma unroll
    for (int o = 64; o > 0; o >>= 1) { if (u < o) red[u] += red[u + o]; __syncthreads(); }
    float rstd = rsqrtf(red[0] / N + 1e-5f);
    float* o1 = out1 + (long)grp*o1Group + (long)rb*N;
    const float* gp = gam + (long)grp*gGroup;
    const float* bp = bet + (long)grp*gGroup;
    for (int t = 0; t < nper; t++) {
        int j = u + t*128;
        float y = (vals[t] - mu)*rstd*gp[j] + bp[j];
        o1[j] = y;
        if (out2) out2[(long)row*N + j] = y;
    }
}

__global__ void clear_k()
{
    long idx = (long)blockIdx.x*256 + threadIdx.x;
    if (idx < (long)P_*L_*B_*d_) {
        g_pa[idx] = 0.f; g_pr[idx] = 0.f; g_dp[idx] = 0.f; g_sr[idx] = 0.f; g_gb[idx] = 0.f;
    }
}

// ---------------- host launcher ----------------
extern "C" void kernel_launch(void* const* d_in, const int* in_sizes, int n_in,
                              void* d_out, int out_size)
{
    const float* x          = (const float*)d_in[0];
    const float* mem0       = (const float*)d_in[1];
    const float* attn_in_w  = (const float*)d_in[2];
    const float* attn_in_b  = (const float*)d_in[3];
    const float* attn_out_w = (const float*)d_in[4];
    const float* attn_out_b = (const float*)d_in[5];
    const float* heb_w      = (const float*)d_in[6];
    const float* heb_rw     = (const float*)d_in[7];
    const float* alpha      = (const float*)d_in[8];
    const float* decay      = (const float*)d_in[9];
    const float* ln_act_g   = (const float*)d_in[10];
    const float* ln_act_b   = (const float*)d_in[11];
    const float* ln_rec_g   = (const float*)d_in[12];
    const float* ln_rec_b   = (const float*)d_in[13];
    const float* pred_w1    = (const float*)d_in[14];
    const float* pred_b1    = (const float*)d_in[15];
    const float* pred_w2    = (const float*)d_in[16];
    const float* pred_b2    = (const float*)d_in[17];
    const float* out_w      = (const float*)d_in[18];
    const float* out_b      = (const float*)d_in[19];
    const float* ln_out_g   = (const float*)d_in[20];
    const float* ln_out_b   = (const float*)d_in[21];

    float *pmem, *pq, *pkv, *po, *pattn, *ph, *pcat, *ppa, *ppr, *pt1, *pnt, *ptmp, *poutpre, *pW, *pWr;
    cudaGetSymbolAddress((void**)&pmem,    g_mem);
    cudaGetSymbolAddress((void**)&pq,      g_q);
    cudaGetSymbolAddress((void**)&pkv,     g_kv);
    cudaGetSymbolAddress((void**)&po,      g_o);
    cudaGetSymbolAddress((void**)&pattn,   g_attn);
    cudaGetSymbolAddress((void**)&ph,      g_h);
    cudaGetSymbolAddress((void**)&pcat,    g_cat);
    cudaGetSymbolAddress((void**)&ppa,     g_pa);
    cudaGetSymbolAddress((void**)&ppr,     g_pr);
    cudaGetSymbolAddress((void**)&pt1,     g_t1);
    cudaGetSymbolAddress((void**)&pnt,     g_nt);
    cudaGetSymbolAddress((void**)&ptmp,    g_tmp);
    cudaGetSymbolAddress((void**)&poutpre, g_outpre);
    cudaGetSymbolAddress((void**)&pW,      g_W);
    cudaGetSymbolAddress((void**)&pWr,     g_Wr);

    const dim3 tb(16, 16);
    const float qscale = 1.f / sqrtf((float)HD_);

    // init state
    cudaMemcpyAsync(pW,  heb_w,  sizeof(float)*(long)P_*L_*d_*d_, cudaMemcpyDeviceToDevice, 0);
    cudaMemcpyAsync(pWr, heb_rw, sizeof(float)*(long)P_*L_*d_*d_, cudaMemcpyDeviceToDevice, 0);
    cudaMemcpyAsync(pmem, mem0,  sizeof(float)*M_*B_*D_,          cudaMemcpyDeviceToDevice, 0);
    clear_k<<<(P_*L_*B_*d_ + 255)/256, 256>>>();

    for (int t = 0; t < T_; t++) {
        const float* xt = x + (long)t*B_*D_;

        // q = (x_t @ wq^T + bq) * scale   [per module m]
        gemm_k<true><<<dim3(12, 1, M_), tb>>>(xt, 0,
            attn_in_w, (long)3*D_*D_, attn_in_b, (long)3*D_, nullptr, 0,
            pq, (long)B_*D_, D_, D_, qscale, 0);
        // kv = mem @ [wk;wv]^T + b       [per m, 256 rows x 1536]
        gemm_k<true><<<dim3(24, 8, M_), tb>>>(pmem, 0,
            attn_in_w + (long)D_*D_, (long)3*D_*D_, attn_in_b + D_, (long)3*D_, nullptr, 0,
            pkv, (long)KVROWS*KVN, KVN, D_, 1.f, 0);
        attn_core_k<<<dim3(H_, B_, M_), 128>>>();
        // o @ out_w^T + out_b
        gemm_k<true><<<dim3(12, 1, M_), tb>>>(po, (long)B_*D_,
            attn_out_w, (long)D_*D_, attn_out_b, (long)D_, nullptr, 0,
            pattn, (long)B_*D_, D_, D_, 1.f, 0);
        a2h_k<<<(P_*B_*d_ + 255)/256, 256>>>();

        for (int l = 0; l < L_; l++) {
            // t1 = relu(pa @ w1 + b1)
            gemm_k<false><<<dim3(6, 1, P_), tb>>>(ppa + (long)l*B_*d_, (long)L_*B_*d_,
                pred_w1 + (long)l*d_*d_, (long)L_*d_*d_, pred_b1 + (long)l*d_, (long)L_*d_,
                nullptr, 0, pt1, (long)B_*d_, d_, d_, 1.f, 1);
            // nt = t1 @ w2 + b2
            gemm_k<false><<<dim3(18, 1, P_), tb>>>(pt1, (long)B_*d_,
                pred_w2 + (long)l*d_*3*d_, (long)L_*d_*3*d_, pred_b2 + (long)l*3*d_, (long)L_*3*d_,
                nullptr, 0, pnt, (long)B_*3*d_, 3*d_, d_, 1.f, 0);
            gates_k<<<(P_*B_*d_ + 255)/256, 256>>>(l, alpha);
            sd_k<<<P_, d_>>>(l, decay);
            rsm_k<<<dim3(P_*B_, 2), 128>>>(l);
            outer_k<<<dim3(6, 12, 2*P_), 256>>>();
            wupd_k<<<dim3(d_, P_, 2), 128>>>(l);
            // rec_pre = pa @ Wr_new
            gemm_k<false><<<dim3(6, 1, P_), tb>>>(ppa + (long)l*B_*d_, (long)L_*B_*d_,
                pWr + (long)l*d_*d_, (long)L_*d_*d_, nullptr, 0, nullptr, 0,
                ptmp, (long)B_*d_, d_, d_, 1.f, 0);
            // pr = LN(rec_pre)
            ln_k<<<P_*B_, 128>>>(ptmp, ppr + (long)l*B_*d_, (long)L_*B_*d_, nullptr,
                ln_rec_g + (long)l*d_, ln_rec_b + (long)l*d_, (long)L_*d_, d_);
            // act_pre = relu(h @ W_new + rec)
            gemm_k<false><<<dim3(6, 1, P_), tb>>>(ph, (long)B_*d_,
                pW + (long)l*d_*d_, (long)L_*d_*d_, nullptr, 0,
                ppr + (long)l*B_*d_, (long)L_*B_*d_,
                ptmp, (long)B_*d_, d_, d_, 1.f, 1);
            // pa = LN(act_pre); h = same
            ln_k<<<P_*B_, 128>>>(ptmp, ppa + (long)l*B_*d_, (long)L_*B_*d_, ph,
                ln_act_g + (long)l*d_, ln_act_b + (long)l*d_, (long)L_*d_, d_);
        }

        h2cat_k<<<(M_*B_*D_ + 255)/256, 256>>>();
        // out = cat @ out_w^T + out_b (einsum mbd,med->mbe)
        gemm_k<true><<<dim3(12, 1, M_), tb>>>(pcat, (long)B_*D_,
            out_w, (long)D_*D_, out_b, (long)D_, nullptr, 0,
            poutpre, (long)B_*D_, D_, D_, 1.f, 0);
        // mem = LN(out)
        ln_k<<<M_*B_, 128>>>(poutpre, pmem, (long)B_*D_, nullptr,
            ln_out_g, ln_out_b, (long)D_, D_);
    }

    cudaMemcpyAsync(d_out, pmem, sizeof(float)*M_*B_*D_, cudaMemcpyDeviceToDevice, 0);
}

// round 2
// speedup vs baseline: 1.3032x; 1.3032x over previous
#include <cuda_runtime.h>
#include <math.h>

// Problem dims
#define T_ 8
#define B_ 32
#define D_ 768
#define M_ 8
#define S_ 2
#define L_ 2
#define H_ 8
#define HD_ 96
#define d_ 384
#define P_ 16          // M_*S_
#define KVROWS 256     // M_*B_
#define KVN 1536       // 2*D_

// ---------------- device state / scratch ----------------
__device__ float g_mem[M_*B_*D_];
__device__ float g_q[M_*B_*D_];
__device__ float g_kv[(long)M_*KVROWS*KVN];
__device__ float g_o[M_*B_*D_];
__device__ float g_attn[M_*B_*D_];
__device__ float g_h[P_*B_*d_];
__device__ float g_cat[M_*B_*D_];
__device__ float g_pa[P_*L_*B_*d_];
__device__ float g_pr[P_*L_*B_*d_];
__device__ float g_dp[P_*L_*B_*d_];
__device__ float g_sr[P_*L_*B_*d_];
__device__ float g_gb[P_*L_*B_*d_];
__device__ float g_W [(long)P_*L_*d_*d_];
__device__ float g_Wr[(long)P_*L_*d_*d_];
__device__ float g_t1[P_*B_*d_];
__device__ float g_nt[P_*B_*3*d_];
__device__ float g_mod[P_*B_*d_];
__device__ float g_asm[2*P_*B_*d_];
__device__ float g_C[(long)2*P_*d_*d_];
__device__ float g_sd[P_*d_];
__device__ float g_tmp[P_*B_*d_];
__device__ float g_outpre[M_*B_*D_];

// ---------------- f32x2 helpers ----------------
__device__ __forceinline__ unsigned long long pack2(float x, float y) {
    unsigned long long r;
    asm("mov.b64 %0, {%1, %2};" : "=l"(r) : "f"(x), "f"(y));
    return r;
}
__device__ __forceinline__ void fma2(unsigned long long& d, unsigned long long a, unsigned long long b) {
    asm("fma.rn.f32x2 %0, %1, %2, %0;" : "+l"(d) : "l"(a), "l"(b));
}
__device__ __forceinline__ float2 unpack2(unsigned long long v) {
    float2 f;
    asm("mov.b64 {%0, %1}, %2;" : "=f"(f.x), "=f"(f.y) : "l"(v));
    return f;
}

// ---------------- generic batched tiled GEMM (f32x2 packed) ----------------
// C[z][i][j] = act( scale*(sum_k opA(A)[i][k]*opB(W)[k][j] + bias[z][j]) + add[z][i][j] )
// TRANSA: A is stored [K, M] with row stride lda  (opA(A)[i][k] = A[k*lda + i])
// else  : A is stored [M, K] with row stride lda  (opA(A)[i][k] = A[i*lda + k])
// TRANSB: W row-major [N, K]  (opB(W)[k][j] = W[j*K + k])
// else  : W row-major [K, N]  (opB(W)[k][j] = W[k*N + j])
// Tile BM=32, BN=64, BK=16; 128 threads; each thread computes 4x4 (packed as 4x2 f32x2).
// Requirements: M%32==0, N%64==0, K%16==0, N%4==0, lda allows float4 loads.
#define AS_STRIDE 36
#define BS_STRIDE 68
template<bool TRANSA, bool TRANSB>
__global__ void gemm2_k(const float* __restrict__ A, long aB, int lda,
                        const float* __restrict__ W, long wB,
                        const float* __restrict__ bias, long bB,
                        const float* __restrict__ add, long adB,
                        float* __restrict__ C, long cB,
                        int N, int K, float scale, int relu)
{
    __shared__ float As[16*AS_STRIDE];
    __shared__ float Bs[16*BS_STRIDE];
    const int tid = threadIdx.x;               // 128
    const int tx = tid & 15;                    // col group (4 cols)
    const int ty = tid >> 4;                    // row group (4 rows)
    const int z = blockIdx.z;
    const float* Ab = A + (long)z*aB;
    const float* Wb = W + (long)z*wB;
    const int row0 = blockIdx.y*32, col0 = blockIdx.x*64;

    unsigned long long acc[4][2];
    #pragma unroll
    for (int r = 0; r < 4; r++) { acc[r][0] = 0ull; acc[r][1] = 0ull; }

    for (int k0 = 0; k0 < K; k0 += 16) {
        // load A tile -> As[kk][row]
        if (TRANSA) {
            int kk = tid >> 3, r4 = (tid & 7)*4;
            float4 av = *(const float4*)&Ab[(long)(k0 + kk)*lda + row0 + r4];
            *(float4*)&As[kk*AS_STRIDE + r4] = av;
        } else {
            int r = tid >> 2, kc = (tid & 3)*4;
            float4 av = *(const float4*)&Ab[(long)(row0 + r)*lda + k0 + kc];
            As[(kc+0)*AS_STRIDE + r] = av.x;
            As[(kc+1)*AS_STRIDE + r] = av.y;
            As[(kc+2)*AS_STRIDE + r] = av.z;
            As[(kc+3)*AS_STRIDE + r] = av.w;
        }
        // load B tile -> Bs[kk][j]
        #pragma unroll
        for (int it = 0; it < 2; it++) {
            int e = tid + it*128;
            if (TRANSB) {
                int j = e >> 2, kc = (e & 3)*4;
                float4 wv = *(const float4*)&Wb[(long)(col0 + j)*K + k0 + kc];
                Bs[(kc+0)*BS_STRIDE + j] = wv.x;
                Bs[(kc+1)*BS_STRIDE + j] = wv.y;
                Bs[(kc+2)*BS_STRIDE + j] = wv.z;
                Bs[(kc+3)*BS_STRIDE + j] = wv.w;
            } else {
                int kk = e >> 4, j4 = (e & 15)*4;
                float4 wv = *(const float4*)&Wb[(long)(k0 + kk)*N + col0 + j4];
                *(float4*)&Bs[kk*BS_STRIDE + j4] = wv;
            }
        }
        __syncthreads();
        #pragma unroll
        for (int kk = 0; kk < 16; kk++) {
            float4 a = *(const float4*)&As[kk*AS_STRIDE + ty*4];
            unsigned long long b0 = *(const unsigned long long*)&Bs[kk*BS_STRIDE + tx*4];
            unsigned long long b1 = *(const unsigned long long*)&Bs[kk*BS_STRIDE + tx*4 + 2];
            unsigned long long a0 = pack2(a.x, a.x);
            unsigned long long a1 = pack2(a.y, a.y);
            unsigned long long a2 = pack2(a.z, a.z);
            unsigned long long a3 = pack2(a.w, a.w);
            fma2(acc[0][0], a0, b0); fma2(acc[0][1], a0, b1);
            fma2(acc[1][0], a1, b0); fma2(acc[1][1], a1, b1);
            fma2(acc[2][0], a2, b0); fma2(acc[2][1], a2, b1);
            fma2(acc[3][0], a3, b0); fma2(acc[3][1], a3, b1);
        }
        __syncthreads();
    }

    float* Cb = C + (long)z*cB;
    #pragma unroll
    for (int r = 0; r < 4; r++) {
        int row = row0 + ty*4 + r;
        int col = col0 + tx*4;
        float2 v0 = unpack2(acc[r][0]);
        float2 v1 = unpack2(acc[r][1]);
        float v[4] = {v0.x, v0.y, v1.x, v1.y};
        #pragma unroll
        for (int c = 0; c < 4; c++) {
            if (bias) v[c] += bias[(long)z*bB + col + c];
            v[c] *= scale;
            if (add)  v[c] += add[(long)z*adB + (long)row*N + col + c];
            if (relu) v[c] = fmaxf(v[c], 0.f);
        }
        *(float4*)&Cb[(long)row*N + col] = make_float4(v[0], v[1], v[2], v[3]);
    }
}

// ---------------- attention core (warp per (h,b,m)) ----------------
__global__ void attn2_k()
{
    int gw = (blockIdx.x*blockDim.x + threadIdx.x) >> 5;
    int lane = threadIdx.x & 31;
    int h = gw & 7;
    int b = (gw >> 3) & 31;
    int m = gw >> 8;
    const float* qb = g_q + ((long)(m*B_ + b))*D_ + h*HD_;
    float q0 = qb[lane], q1 = qb[lane + 32], q2 = qb[lane + 64];
    float a[M_];
    #pragma unroll
    for (int s = 0; s < M_; s++) {
        const float* kb = g_kv + ((long)m*KVROWS + s*B_ + b)*KVN + h*HD_;
        float p = q0*kb[lane] + q1*kb[lane + 32] + q2*kb[lane + 64];
        #pragma unroll
        for (int o = 16; o > 0; o >>= 1) p += __shfl_xor_sync(0xffffffffu, p, o);
        a[s] = p;
    }
    float mx = -1e30f;
    #pragma unroll
    for (int s = 0; s < M_; s++) mx = fmaxf(mx, a[s]);
    float sum = 0.f;
    #pragma unroll
    for (int s = 0; s < M_; s++) { a[s] = __expf(a[s] - mx); sum += a[s]; }
    float inv = 1.f / sum;
    float o0 = 0.f, o1 = 0.f, o2 = 0.f;
    #pragma unroll
    for (int s = 0; s < M_; s++) {
        const float* vb = g_kv + ((long)m*KVROWS + s*B_ + b)*KVN + D_ + h*HD_;
        float av = a[s]*inv;
        o0 += av*vb[lane]; o1 += av*vb[lane + 32]; o2 += av*vb[lane + 64];
    }
    float* ob = g_o + ((long)(m*B_ + b))*D_ + h*HD_;
    ob[lane] = o0; ob[lane + 32] = o1; ob[lane + 64] = o2;
}

// ---------------- reshapes ----------------
__global__ void a2h_k()
{
    int idx = blockIdx.x*256 + threadIdx.x;
    if (idx >= P_*B_*d_) return;
    int j = idx % d_; int b = (idx/d_) % B_; int p = idx/(B_*d_);
    int m = p / S_, s = p % S_;
    g_h[idx] = g_attn[((long)(m*B_ + b))*D_ + s*d_ + j];
}
__global__ void h2cat_k()
{
    int idx = blockIdx.x*256 + threadIdx.x;
    if (idx >= M_*B_*D_) return;
    int j = idx % d_; int s = (idx/d_) % S_; int b = (idx/D_) % B_; int m = idx/(B_*D_);
    g_cat[idx] = g_h[((long)((m*S_ + s)*B_ + b))*d_ + j];
}

// ---------------- plastic layer kernels ----------------
__global__ void gates_k(int l, const float* __restrict__ alpha)
{
    int idx = blockIdx.x*256 + threadIdx.x;
    if (idx >= P_*B_*d_) return;
    int j = idx % d_; int b = (idx/d_) % B_; int p = idx/(B_*d_);
    int pl = p*L_ + l;
    long sidx = ((long)pl*B_ + b)*d_ + j;
    const float* nt = g_nt + ((long)(p*B_ + b))*3*d_ + j*3;
    float pd = nt[0], ps = nt[1], pg = nt[2];
    float inv = 1.f / fmaxf(ps, 1e-6f);
    float dpv = tanhf(g_dp[sidx] + pd*inv);
    float srv = 1.f/(1.f + __expf(-(g_sr[sidx] + ps)));
    float gbv = 1.f/(1.f + __expf(-(g_gb[sidx] + pg*inv)));
    g_dp[sidx] = dpv; g_sr[sidx] = srv; g_gb[sidx] = gbv;
    g_mod[(long)(p*B_ + b)*d_ + j] = alpha[(long)pl*d_ + j] * dpv * srv;
}

__global__ void sd_k(int l, const float* __restrict__ decay)
{
    int p = blockIdx.x; int j = threadIdx.x; // 384 threads
    int pl = p*L_ + l;
    float s = 0.f;
    for (int b = 0; b < B_; b++) s += g_gb[((long)pl*B_ + b)*d_ + j];
    s *= (1.f/B_);
    g_sd[p*d_ + j] = decay[(long)pl*d_ + j] * (1.f/(1.f + __expf(-s)));
}

__global__ void rsm_k(int l)   // row softmax of pa (which=0) / pr (which=1) over d_
{
    int row = blockIdx.x;      // 0..P_*B_-1
    int which = blockIdx.y;
    int p = row / B_, b = row % B_;
    const float* src = (which ? g_pr : g_pa) + ((long)(p*L_ + l)*B_ + b)*d_;
    float* dst = g_asm + (long)which*P_*B_*d_ + (long)row*d_;
    int u = threadIdx.x;       // 128
    __shared__ float red[128];
    float v0 = src[u], v1 = src[u + 128], v2 = src[u + 256];
    float mx = fmaxf(v0, fmaxf(v1, v2));
    red[u] = mx; __syncthreads();
    #pragma unroll
    for (int o = 64; o > 0; o >>= 1) { if (u < o) red[u] = fmaxf(red[u], red[u + o]); __syncthreads(); }
    mx = red[0]; __syncthreads();
    float e0 = __expf(v0 - mx), e1 = __expf(v1 - mx), e2 = __expf(v2 - mx);
    red[u] = e0 + e1 + e2; __syncthreads();
    #pragma unroll
    for (int o = 64; o > 0; o >>= 1) { if (u < o) red[u] += red[u + o]; __syncthreads(); }
    float inv = 1.f / red[0];
    dst[u] = e0*inv; dst[u + 128] = e1*inv; dst[u + 256] = e2*inv;
}

// W_new[i][j] = W*(1-sd[i]) + rowsoftmax(W)[i][j]*C[i][j]
__global__ void wupd_k(int l)
{
    int i = blockIdx.x, p = blockIdx.y, which = blockIdx.z;
    float* Wp = (which ? g_Wr : g_W) + ((long)(p*L_ + l)*d_ + i)*d_;
    const float* Cp = g_C + ((long)(which*P_ + p)*d_ + i)*d_;
    int u = threadIdx.x;  // 128
    __shared__ float red[128];
    float w0 = Wp[u], w1 = Wp[u + 128], w2 = Wp[u + 256];
    float mx = fmaxf(w0, fmaxf(w1, w2));
    red[u] = mx; __syncthreads();
    #pragma unroll
    for (int o = 64; o > 0; o >>= 1) { if (u < o) red[u] = fmaxf(red[u], red[u + o]); __syncthreads(); }
    mx = red[0]; __syncthreads();
    float e0 = __expf(w0 - mx), e1 = __expf(w1 - mx), e2 = __expf(w2 - mx);
    red[u] = e0 + e1 + e2; __syncthreads();
    #pragma unroll
    for (int o = 64; o > 0; o >>= 1) { if (u < o) red[u] += red[u + o]; __syncthreads(); }
    float invs = 1.f / red[0];
    float om = 1.f - g_sd[p*d_ + i];
    Wp[u]       = w0*om + e0*invs*Cp[u];
    Wp[u + 128] = w1*om + e1*invs*Cp[u + 128];
    Wp[u + 256] = w2*om + e2*invs*Cp[u + 256];
}

// ---------------- LayerNorm ----------------
__global__ void ln_k(const float* __restrict__ in,
                     float* __restrict__ out1, long o1Group,
                     float* __restrict__ out2,
                     const float* __restrict__ gam, const float* __restrict__ bet,
                     long gGroup, int N)
{
    int row = blockIdx.x;
    int u = threadIdx.x;   // 128
    int grp = row / B_, rb = row % B_;
    const float* x = in + (long)row*N;
    int nper = N / 128;    // 3 or 6
    float vals[6];
    float s = 0.f;
    for (int t = 0; t < nper; t++) { vals[t] = x[u + t*128]; s += vals[t]; }
    __shared__ float red[128];
    red[u] = s; __syncthreads();
    #pragma unroll
    for (int o = 64; o > 0; o >>= 1) { if (u < o) red[u] += red[u + o]; __syncthreads(); }
    float mu = red[0] / N; __syncthreads();
    float sq = 0.f;
    for (int t = 0; t < nper; t++) { float dv = vals[t] - mu; sq += dv*dv; }
    red[u] = sq; __syncthreads();
    #pragma unroll
    for (int o = 64; o > 0; o >>= 1) { if (u < o) red[u] += red[u + o]; __syncthreads(); }
    float rstd = rsqrtf(red[0] / N + 1e-5f);
    float* o1 = out1 + (long)grp*o1Group + (long)rb*N;
    const float* gp = gam + (long)grp*gGroup;
    const float* bp = bet + (long)grp*gGroup;
    for (int t = 0; t < nper; t++) {
        int j = u + t*128;
        float y = (vals[t] - mu)*rstd*gp[j] + bp[j];
        o1[j] = y;
        if (out2) out2[(long)row*N + j] = y;
    }
}

__global__ void clear_k()
{
    long idx = (long)blockIdx.x*256 + threadIdx.x;
    if (idx < (long)P_*L_*B_*d_) {
        g_pa[idx] = 0.f; g_pr[idx] = 0.f; g_dp[idx] = 0.f; g_sr[idx] = 0.f; g_gb[idx] = 0.f;
    }
}

// ---------------- host launcher ----------------
extern "C" void kernel_launch(void* const* d_in, const int* in_sizes, int n_in,
                              void* d_out, int out_size)
{
    const float* x          = (const float*)d_in[0];
    const float* mem0       = (const float*)d_in[1];
    const float* attn_in_w  = (const float*)d_in[2];
    const float* attn_in_b  = (const float*)d_in[3];
    const float* attn_out_w = (const float*)d_in[4];
    const float* attn_out_b = (const float*)d_in[5];
    const float* heb_w      = (const float*)d_in[6];
    const float* heb_rw     = (const float*)d_in[7];
    const float* alpha      = (const float*)d_in[8];
    const float* decay      = (const float*)d_in[9];
    const float* ln_act_g   = (const float*)d_in[10];
    const float* ln_act_b   = (const float*)d_in[11];
    const float* ln_rec_g   = (const float*)d_in[12];
    const float* ln_rec_b   = (const float*)d_in[13];
    const float* pred_w1    = (const float*)d_in[14];
    const float* pred_b1    = (const float*)d_in[15];
    const float* pred_w2    = (const float*)d_in[16];
    const float* pred_b2    = (const float*)d_in[17];
    const float* out_w      = (const float*)d_in[18];
    const float* out_b      = (const float*)d_in[19];
    const float* ln_out_g   = (const float*)d_in[20];
    const float* ln_out_b   = (const float*)d_in[21];

    float *pmem, *pq, *pkv, *po, *pattn, *ph, *pcat, *ppa, *ppr, *pt1, *pnt, *ptmp,
          *poutpre, *pW, *pWr, *pasm, *pmod, *pC;
    cudaGetSymbolAddress((void**)&pmem,    g_mem);
    cudaGetSymbolAddress((void**)&pq,      g_q);
    cudaGetSymbolAddress((void**)&pkv,     g_kv);
    cudaGetSymbolAddress((void**)&po,      g_o);
    cudaGetSymbolAddress((void**)&pattn,   g_attn);
    cudaGetSymbolAddress((void**)&ph,      g_h);
    cudaGetSymbolAddress((void**)&pcat,    g_cat);
    cudaGetSymbolAddress((void**)&ppa,     g_pa);
    cudaGetSymbolAddress((void**)&ppr,     g_pr);
    cudaGetSymbolAddress((void**)&pt1,     g_t1);
    cudaGetSymbolAddress((void**)&pnt,     g_nt);
    cudaGetSymbolAddress((void**)&ptmp,    g_tmp);
    cudaGetSymbolAddress((void**)&poutpre, g_outpre);
    cudaGetSymbolAddress((void**)&pW,      g_W);
    cudaGetSymbolAddress((void**)&pWr,     g_Wr);
    cudaGetSymbolAddress((void**)&pasm,    g_asm);
    cudaGetSymbolAddress((void**)&pmod,    g_mod);
    cudaGetSymbolAddress((void**)&pC,      g_C);

    const float qscale = 1.f / sqrtf((float)HD_);

    // init state
    cudaMemcpyAsync(pW,  heb_w,  sizeof(float)*(long)P_*L_*d_*d_, cudaMemcpyDeviceToDevice, 0);
    cudaMemcpyAsync(pWr, heb_rw, sizeof(float)*(long)P_*L_*d_*d_, cudaMemcpyDeviceToDevice, 0);
    cudaMemcpyAsync(pmem, mem0,  sizeof(float)*M_*B_*D_,          cudaMemcpyDeviceToDevice, 0);
    clear_k<<<(P_*L_*B_*d_ + 255)/256, 256>>>();

    for (int t = 0; t < T_; t++) {
        const float* xt = x + (long)t*B_*D_;

        // q = (x_t @ wq^T + bq) * qscale   [per module m]
        gemm2_k<false,true><<<dim3(12, 1, M_), 128>>>(xt, 0, D_,
            attn_in_w, (long)3*D_*D_, attn_in_b, (long)3*D_, nullptr, 0,
            pq, (long)B_*D_, D_, D_, qscale, 0);
        // kv = mem @ [wk;wv]^T + b        [per m, 256 x 1536]
        gemm2_k<false,true><<<dim3(24, 8, M_), 128>>>(pmem, 0, D_,
            attn_in_w + (long)D_*D_, (long)3*D_*D_, attn_in_b + D_, (long)3*D_, nullptr, 0,
            pkv, (long)KVROWS*KVN, KVN, D_, 1.f, 0);
        attn2_k<<<256, 256>>>();
        // attn = o @ out_w^T + out_b
        gemm2_k<false,true><<<dim3(12, 1, M_), 128>>>(po, (long)B_*D_, D_,
            attn_out_w, (long)D_*D_, attn_out_b, (long)D_, nullptr, 0,
            pattn, (long)B_*D_, D_, D_, 1.f, 0);
        a2h_k<<<(P_*B_*d_ + 255)/256, 256>>>();

        for (int l = 0; l < L_; l++) {
            // t1 = relu(pa @ w1 + b1)
            gemm2_k<false,false><<<dim3(6, 1, P_), 128>>>(ppa + (long)l*B_*d_, (long)L_*B_*d_, d_,
                pred_w1 + (long)l*d_*d_, (long)L_*d_*d_, pred_b1 + (long)l*d_, (long)L_*d_,
                nullptr, 0, pt1, (long)B_*d_, d_, d_, 1.f, 1);
            // nt = t1 @ w2 + b2
            gemm2_k<false,false><<<dim3(18, 1, P_), 128>>>(pt1, (long)B_*d_, d_,
                pred_w2 + (long)l*d_*3*d_, (long)L_*d_*3*d_, pred_b2 + (long)l*3*d_, (long)L_*3*d_,
                nullptr, 0, pnt, (long)B_*3*d_, 3*d_, d_, 1.f, 0);
            gates_k<<<(P_*B_*d_ + 255)/256, 256>>>(l, alpha);
            sd_k<<<P_, d_>>>(l, decay);
            rsm_k<<<dim3(P_*B_, 2), 128>>>(l);
            // C[z] = (1/B) * asm[z]^T @ mod[z]   (TRANSA: A is [K=B][M=d])
            gemm2_k<true,false><<<dim3(6, 12, P_), 128>>>(pasm, (long)B_*d_, d_,
                pmod, (long)B_*d_, nullptr, 0, nullptr, 0,
                pC, (long)d_*d_, d_, B_, 1.f/B_, 0);
            gemm2_k<true,false><<<dim3(6, 12, P_), 128>>>(pasm + (long)P_*B_*d_, (long)B_*d_, d_,
                pmod, (long)B_*d_, nullptr, 0, nullptr, 0,
                pC + (long)P_*d_*d_, (long)d_*d_, d_, B_, 1.f/B_, 0);
            wupd_k<<<dim3(d_, P_, 2), 128>>>(l);
            // rec_pre = pa @ Wr_new
            gemm2_k<false,false><<<dim3(6, 1, P_), 128>>>(ppa + (long)l*B_*d_, (long)L_*B_*d_, d_,
                pWr + (long)l*d_*d_, (long)L_*d_*d_, nullptr, 0, nullptr, 0,
                ptmp, (long)B_*d_, d_, d_, 1.f, 0);
            // pr = LN(rec_pre)
            ln_k<<<P_*B_, 128>>>(ptmp, ppr + (long)l*B_*d_, (long)L_*B_*d_, nullptr,
                ln_rec_g + (long)l*d_, ln_rec_b + (long)l*d_, (long)L_*d_, d_);
            // act_pre = relu(h @ W_new + rec)
            gemm2_k<false,false><<<dim3(6, 1, P_), 128>>>(ph, (long)B_*d_, d_,
                pW + (long)l*d_*d_, (long)L_*d_*d_, nullptr, 0,
                ppr + (long)l*B_*d_, (long)L_*B_*d_,
                ptmp, (long)B_*d_, d_, d_, 1.f, 1);
            // pa = LN(act_pre); h = same values
            ln_k<<<P_*B_, 128>>>(ptmp, ppa + (long)l*B_*d_, (long)L_*B_*d_, ph,
                ln_act_g + (long)l*d_, ln_act_b + (long)l*d_, (long)L_*d_, d_);
        }

        h2cat_k<<<(M_*B_*D_ + 255)/256, 256>>>();
        // out = cat @ out_w^T + out_b
        gemm2_k<false,true><<<dim3(12, 1, M_), 128>>>(pcat, (long)B_*D_, D_,
            out_w, (long)D_*D_, out_b, (long)D_, nullptr, 0,
            poutpre, (long)B_*D_, D_, D_, 1.f, 0);
        // mem = LN(out)
        ln_k<<<M_*B_, 128>>>(poutpre, pmem, (long)B_*D_, nullptr,
            ln_out_g, ln_out_b, (long)D_, D_);
    }

    cudaMemcpyAsync(d_out, pmem, sizeof(float)*M_*B_*D_, cudaMemcpyDeviceToDevice, 0);
}